// round 10
// baseline (speedup 1.0000x reference)
#include <cuda_runtime.h>
#include <math.h>
#include <stdint.h>

// Problem constants
#define Bc 2
#define Tc 2048
#define Dc 2048
#define Hc 16
#define MROWS (Bc*Tc)          // 4096

// ---------------- scratch (device globals; no allocation allowed) -------------
__device__ float g_qs[MROWS * 1024];
__device__ float g_ks[MROWS * 1024];
__device__ float g_qg[MROWS * 1024];
__device__ float g_kg[MROWS * 1024];
__device__ float g_vt[MROWS * 2048];           // V, tf32-rounded
__device__ float g_qcat[Bc*Hc*Tc*128];         // Q, tf32-rounded
__device__ float g_kt  [Bc*Hc*Tc*128];         // K, tf32-rounded
__device__ float g_ao [MROWS * 2048];          // attn out, tf32-rounded
// pre-rounded operands
__device__ float g_xr  [MROWS * 2048];
__device__ float g_wqs [2048 * 1024];
__device__ float g_wks [2048 * 1024];
__device__ float g_wqg [2048 * 1024];
__device__ float g_wkg [2048 * 1024];
__device__ float g_wv  [2048 * 2048];
__device__ float g_wo  [2048 * 2048];

// ---------------- tf32 helpers -------------------------------------------------
__device__ __forceinline__ uint32_t f2tf32(float f) {
    uint32_t u;
    asm("cvt.rna.tf32.f32 %0, %1;" : "=r"(u) : "f"(f));
    return u;
}
__device__ __forceinline__ float tf32r(float x) {
    return __uint_as_float(f2tf32(x));
}

__device__ __forceinline__ void mma_tf32(float* c,
                                         uint32_t a0, uint32_t a1, uint32_t a2, uint32_t a3,
                                         uint32_t b0, uint32_t b1) {
    asm volatile("mma.sync.aligned.m16n8k8.row.col.f32.tf32.tf32.f32 "
                 "{%0,%1,%2,%3}, {%4,%5,%6,%7}, {%8,%9}, {%0,%1,%2,%3};"
                 : "+f"(c[0]), "+f"(c[1]), "+f"(c[2]), "+f"(c[3])
                 : "r"(a0), "r"(a1), "r"(a2), "r"(a3), "r"(b0), "r"(b1));
}

__device__ __forceinline__ void cp16(void* dst, const void* src) {
    uint32_t d = (uint32_t)__cvta_generic_to_shared(dst);
    asm volatile("cp.async.cg.shared.global [%0], [%1], 16;" :: "r"(d), "l"(src));
}
__device__ __forceinline__ void cp_commit() {
    asm volatile("cp.async.commit_group;");
}
__device__ __forceinline__ void cp_wait1() {
    asm volatile("cp.async.wait_group 1;");
}
__device__ __forceinline__ void cp_wait0() {
    asm volatile("cp.async.wait_group 0;");
}

// ---------------- pre-round pass: tf32(RNA) copies of x and weights -----------
__global__ __launch_bounds__(256) void round_all(
    const float* __restrict__ x,
    const float* __restrict__ w0, const float* __restrict__ w1,
    const float* __restrict__ w2, const float* __restrict__ w3,
    const float* __restrict__ wv, const float* __restrict__ wo,
    float* __restrict__ xr,
    float* __restrict__ w0r, float* __restrict__ w1r,
    float* __restrict__ w2r, float* __restrict__ w3r,
    float* __restrict__ wvr, float* __restrict__ wor)
{
    const int z = blockIdx.z;
    const float* src; float* dst; int n4;
    switch (z) {
        case 0: src = x;  dst = xr;  n4 = MROWS * 2048 / 4; break;
        case 1: src = w0; dst = w0r; n4 = 2048 * 1024 / 4;  break;
        case 2: src = w1; dst = w1r; n4 = 2048 * 1024 / 4;  break;
        case 3: src = w2; dst = w2r; n4 = 2048 * 1024 / 4;  break;
        case 4: src = w3; dst = w3r; n4 = 2048 * 1024 / 4;  break;
        case 5: src = wv; dst = wvr; n4 = 2048 * 2048 / 4;  break;
        default:src = wo; dst = wor; n4 = 2048 * 2048 / 4;  break;
    }
    const int stride = gridDim.x * blockDim.x;
    for (int i = blockIdx.x * blockDim.x + threadIdx.x; i < n4; i += stride) {
        float4 v = *(const float4*)(src + (size_t)i * 4);
        v.x = tf32r(v.x); v.y = tf32r(v.y); v.z = tf32r(v.z); v.w = tf32r(v.w);
        *(float4*)(dst + (size_t)i * 4) = v;
    }
}

// ---------------- gemm3: cp.async-fed tf32 GEMM --------------------------------
// Operands MUST be pre-rounded tf32 bits. 128 threads, warp tile 64x64,
// BK=16, 3-stage cp.async ring, one __syncthreads per K-iter.
#define G3_ASTR 20
#define G3_BSTR 136
#define G3_ABUF (128*G3_ASTR)
#define G3_BBUF (16*G3_BSTR)
#define G3_STAGE (G3_ABUF + G3_BBUF)
#define G3_SMEM_BYTES (3*G3_STAGE*4)   // 56,832 B

__device__ __forceinline__ void gemm3_core(
    const float* __restrict__ A, const float* __restrict__ B,
    float* __restrict__ C, int K, int ldb, int ldc, int roundC,
    float* sm, int bm, int bn)
{
    const int tid  = threadIdx.x;
    const int lane = tid & 31;
    const int wid  = tid >> 5;
    const int warpRow = (wid >> 1) * 64;
    const int warpCol = (wid & 1) * 64;
    const int g = lane >> 2;
    const int t = lane & 3;

    float acc[4][8][4];
    #pragma unroll
    for (int i = 0; i < 4; i++)
        #pragma unroll
        for (int j = 0; j < 8; j++)
            #pragma unroll
            for (int r = 0; r < 4; r++) acc[i][j][r] = 0.f;

    const int nkt = K / 16;

    // prologue: stages 0, 1
    #pragma unroll
    for (int pre = 0; pre < 2; pre++) {
        float* sA = sm + pre * G3_STAGE;
        float* sB = sA + G3_ABUF;
        const int k0 = pre * 16;
        #pragma unroll
        for (int c = 0; c < 4; c++)
            cp16(&sA[tid * G3_ASTR + c * 4], A + (size_t)(bm + tid) * K + k0 + c * 4);
        #pragma unroll
        for (int j = 0; j < 4; j++) {
            const int i = tid + j * 128;
            const int r = i >> 5, c4 = (i & 31) * 4;
            cp16(&sB[r * G3_BSTR + c4], B + (size_t)(k0 + r) * ldb + bn + c4);
        }
        cp_commit();
    }

    int s_cur = 0, s_pre = 2;
    for (int kt = 0; kt < nkt; kt++) {
        if (kt + 1 < nkt) cp_wait1(); else cp_wait0();
        __syncthreads();

        if (kt + 2 < nkt) {
            float* sA = sm + s_pre * G3_STAGE;
            float* sB = sA + G3_ABUF;
            const int k0 = (kt + 2) * 16;
            #pragma unroll
            for (int c = 0; c < 4; c++)
                cp16(&sA[tid * G3_ASTR + c * 4], A + (size_t)(bm + tid) * K + k0 + c * 4);
            #pragma unroll
            for (int j = 0; j < 4; j++) {
                const int i = tid + j * 128;
                const int r = i >> 5, c4 = (i & 31) * 4;
                cp16(&sB[r * G3_BSTR + c4], B + (size_t)(k0 + r) * ldb + bn + c4);
            }
            cp_commit();
        }

        const uint32_t* uA = (const uint32_t*)(sm + s_cur * G3_STAGE);
        const uint32_t* uB = uA + G3_ABUF;

        #pragma unroll
        for (int ks = 0; ks < 2; ks++) {
            const int kb = ks * 8;
            uint32_t af[4][4], bf[8][2];
            #pragma unroll
            for (int am = 0; am < 4; am++) {
                const int r0 = warpRow + am*16 + g;
                af[am][0] = uA[ r0      * G3_ASTR + kb + t];
                af[am][1] = uA[(r0 + 8) * G3_ASTR + kb + t];
                af[am][2] = uA[ r0      * G3_ASTR + kb + t + 4];
                af[am][3] = uA[(r0 + 8) * G3_ASTR + kb + t + 4];
            }
            #pragma unroll
            for (int an = 0; an < 8; an++) {
                const int c0 = warpCol + an*8 + g;
                bf[an][0] = uB[(kb + t    ) * G3_BSTR + c0];
                bf[an][1] = uB[(kb + t + 4) * G3_BSTR + c0];
            }
            #pragma unroll
            for (int am = 0; am < 4; am++)
                #pragma unroll
                for (int an = 0; an < 8; an++)
                    mma_tf32(acc[am][an], af[am][0], af[am][1], af[am][2], af[am][3],
                             bf[an][0], bf[an][1]);
        }

        s_cur = (s_cur == 2) ? 0 : s_cur + 1;
        s_pre = (s_pre == 2) ? 0 : s_pre + 1;
    }

    #pragma unroll
    for (int am = 0; am < 4; am++) {
        const int r0 = bm + warpRow + am*16 + g;
        #pragma unroll
        for (int an = 0; an < 8; an++) {
            const int c0 = bn + warpCol + an*8 + t*2;
            float v0 = acc[am][an][0], v1 = acc[am][an][1];
            float v2 = acc[am][an][2], v3 = acc[am][an][3];
            if (roundC) { v0 = tf32r(v0); v1 = tf32r(v1); v2 = tf32r(v2); v3 = tf32r(v3); }
            *(float2*)(C + (size_t)r0 * ldc + c0)       = make_float2(v0, v1);
            *(float2*)(C + (size_t)(r0 + 8) * ldc + c0) = make_float2(v2, v3);
        }
    }
}

// all 5 projections in one launch: z 0..3 = Q/K (N=1024), z 4..5 = Wv halves
__global__ __launch_bounds__(128, 2) void gemm3_proj(
    const float* __restrict__ xr,
    const float* __restrict__ B0, const float* __restrict__ B1,
    const float* __restrict__ B2, const float* __restrict__ B3,
    const float* __restrict__ Bv,
    float* __restrict__ C0, float* __restrict__ C1,
    float* __restrict__ C2, float* __restrict__ C3,
    float* __restrict__ Cv)
{
    extern __shared__ float sm[];
    const int z = blockIdx.z;
    const float* B; float* C; int ldb, ldc, roundC;
    if (z < 4) {
        B = (z == 0) ? B0 : (z == 1) ? B1 : (z == 2) ? B2 : B3;
        C = (z == 0) ? C0 : (z == 1) ? C1 : (z == 2) ? C2 : C3;
        ldb = 1024; ldc = 1024; roundC = 0;
    } else {
        B = Bv + (z - 4) * 1024;
        C = Cv + (z - 4) * 1024;
        ldb = 2048; ldc = 2048; roundC = 1;
    }
    gemm3_core(xr, B, C, 2048, ldb, ldc, roundC, sm,
               blockIdx.y * 128, blockIdx.x * 128);
}

__global__ __launch_bounds__(128, 2) void gemm3(
    const float* __restrict__ A, const float* __restrict__ B,
    float* __restrict__ C, int K, int ldb, int ldc, int roundC)
{
    extern __shared__ float sm[];
    gemm3_core(A, B, C, K, ldb, ldc, roundC, sm,
               blockIdx.y * 128, blockIdx.x * 128);
}

// ---------------- RoPE + gate fusion: Q and K both tf32-rounded ----------------
__global__ __launch_bounds__(256) void fuse_rope(
    const float* __restrict__ qs, const float* __restrict__ ks,
    const float* __restrict__ qg, const float* __restrict__ kg,
    const float* __restrict__ gate_logit,
    const int* __restrict__ pos_offset,
    float* __restrict__ qcat, float* __restrict__ kt_o)
{
    const int row = blockIdx.x * 4 + (threadIdx.x >> 6);   // (b*H + h)*T + t
    const int d   = threadIdx.x & 63;
    const int t   = row % Tc;
    const int h   = (row / Tc) % Hc;
    const int b   = row / (Tc * Hc);

    const size_t src = ((size_t)(b * Tc + t)) * 1024 + h * 64 + d;
    const size_t dst = (size_t)row * 128;

    const float gate = 1.f / (1.f + __expf(-gate_logit[h]));
    const float scale = 0.125f;              // 1/sqrt(64)
    const float gq_sem = 2.f * gate * scale;
    const float gq_geo = (2.f - 2.f * gate) * scale;

    qcat[dst + d] = tf32r(qs[src] * gq_sem);
    kt_o[dst + d] = tf32r(ks[src]);

    if (d < 32) {
        const float inv_freq = powf(10000.f, -(float)d / 32.f);
        const float ang = ((float)t + (float)(*pos_offset)) * inv_freq;
        const float c = cosf(ang), s = sinf(ang);
        const float q1 = qg[src], q2 = qg[src + 32];
        const float k1 = kg[src], k2 = kg[src + 32];
        qcat[dst + 64 + d]      = tf32r((q1 * c - q2 * s) * gq_geo);
        qcat[dst + 64 + d + 32] = tf32r((q2 * c + q1 * s) * gq_geo);
        kt_o[dst + 64 + d]      = tf32r(k1 * c - k2 * s);
        kt_o[dst + 64 + d + 32] = tf32r(k2 * c + k1 * s);
    }
}

// ---------------- Flash attention v6 (epilogue now emits tf32-rounded) ---------
#define F6_KSTR 132
#define F6_VSTR 136
#define F6_KBUF (64*F6_KSTR)
#define F6_VBUF (64*F6_VSTR)
#define F6_STAGE (F6_KBUF + F6_VBUF)
#define F6_SMEM_FLOATS (3 * F6_STAGE)
#define F6_SMEM_BYTES  (F6_SMEM_FLOATS * 4)   // 205,824 B

__global__ __launch_bounds__(256, 1) void flash6(
    const float* __restrict__ Qc,
    const float* __restrict__ Ktg,
    const float* __restrict__ Vtg,
    float* __restrict__ Out)
{
    extern __shared__ float sm[];

    const int qb = gridDim.x - 1 - blockIdx.x;   // heavy CTAs first
    const int bh = blockIdx.y;
    const int b  = bh >> 4, h = bh & 15;
    const int tid  = threadIdx.x;
    const int lane = tid & 31;
    const int wid  = tid >> 5;
    const int g = lane >> 2;
    const int t = lane & 3;
    const int r0 = wid * 16 + g;

    const float* Qg  = Qc  + ((size_t)bh * Tc + qb * 128) * 128;
    const float* Kp  = Ktg + (size_t)bh * Tc * 128;
    const float* Vp  = Vtg + (size_t)b * Tc * 2048 + h * 128;

    for (int i = tid; i < 4096; i += 256) {
        const int r = i >> 5, c4 = (i & 31) << 2;
        *(float4*)&sm[r * F6_KSTR + c4] = *(const float4*)(Qg + r * 128 + c4);
    }
    __syncthreads();
    uint32_t qf[16][4];
    #pragma unroll
    for (int ks = 0; ks < 16; ks++) {
        qf[ks][0] = f2tf32(sm[ r0      * F6_KSTR + ks*8 + t]);
        qf[ks][1] = f2tf32(sm[(r0 + 8) * F6_KSTR + ks*8 + t]);
        qf[ks][2] = f2tf32(sm[ r0      * F6_KSTR + ks*8 + t + 4]);
        qf[ks][3] = f2tf32(sm[(r0 + 8) * F6_KSTR + ks*8 + t + 4]);
    }
    __syncthreads();

    const int ntiles = 2 * qb + 2;

    #pragma unroll
    for (int pre = 0; pre < 2; pre++) {
        float* dK = sm + pre * F6_STAGE;
        float* dV = dK + F6_KBUF;
        #pragma unroll
        for (int j = 0; j < 8; j++) {
            const int i = tid + j * 256;
            const int r = i >> 5, c4 = (i & 31) << 2;
            const size_t krow = (size_t)(pre * 64 + r);
            cp16(&dK[r*F6_KSTR + c4], Kp + krow*128  + c4);
            cp16(&dV[r*F6_VSTR + c4], Vp + krow*2048 + c4);
        }
        cp_commit();
    }

    float oreg[16][4];
    #pragma unroll
    for (int n = 0; n < 16; n++) {
        oreg[n][0] = 0.f; oreg[n][1] = 0.f; oreg[n][2] = 0.f; oreg[n][3] = 0.f;
    }
    float M0 = -1e30f, M1 = -1e30f, L0 = 0.f, L1 = 0.f;

    const int srcA = (lane & 28) | (t >> 1);
    const int srcB = srcA + 2;
    const bool odd = (t & 1);

    int s_cur = 0, s_pre = 2;
    for (int kt = 0; kt < ntiles; kt++) {
        if (kt + 1 < ntiles) cp_wait1(); else cp_wait0();
        __syncthreads();

        if (kt + 2 < ntiles) {
            float* dK = sm + s_pre * F6_STAGE;
            float* dV = dK + F6_KBUF;
            #pragma unroll
            for (int j = 0; j < 8; j++) {
                const int i = tid + j * 256;
                const int r = i >> 5, c4 = (i & 31) << 2;
                const size_t krow = (size_t)((kt + 2) * 64 + r);
                cp16(&dK[r*F6_KSTR + c4], Kp + krow*128  + c4);
                cp16(&dV[r*F6_VSTR + c4], Vp + krow*2048 + c4);
            }
            cp_commit();
        }

        const uint32_t* uK = (const uint32_t*)(sm + s_cur * F6_STAGE);
        const uint32_t* uV = uK + F6_KBUF;

        float sreg[8][4];
        #pragma unroll
        for (int n = 0; n < 8; n++) {
            sreg[n][0] = 0.f; sreg[n][1] = 0.f; sreg[n][2] = 0.f; sreg[n][3] = 0.f;
        }
        #pragma unroll
        for (int ks = 0; ks < 16; ks++) {
            const int kb = ks*8 + t;
            #pragma unroll
            for (int n = 0; n < 8; n++) {
                const int kr = n*8 + g;
                mma_tf32(sreg[n], qf[ks][0], qf[ks][1], qf[ks][2], qf[ks][3],
                         uK[kr*F6_KSTR + kb], uK[kr*F6_KSTR + kb + 4]);
            }
        }

        if (kt >= 2 * qb) {
            const int qrow0 = qb * 128 + r0;
            const int qrow1 = qrow0 + 8;
            #pragma unroll
            for (int n = 0; n < 8; n++) {
                const int c = kt * 64 + n*8 + 2*t;
                if (c     > qrow0) sreg[n][0] = -1e30f;
                if (c + 1 > qrow0) sreg[n][1] = -1e30f;
                if (c     > qrow1) sreg[n][2] = -1e30f;
                if (c + 1 > qrow1) sreg[n][3] = -1e30f;
            }
        }

        float mx0 = -1e30f, mx1 = -1e30f;
        #pragma unroll
        for (int n = 0; n < 8; n++) {
            mx0 = fmaxf(mx0, fmaxf(sreg[n][0], sreg[n][1]));
            mx1 = fmaxf(mx1, fmaxf(sreg[n][2], sreg[n][3]));
        }
        mx0 = fmaxf(mx0, __shfl_xor_sync(0xffffffffu, mx0, 1));
        mx0 = fmaxf(mx0, __shfl_xor_sync(0xffffffffu, mx0, 2));
        mx1 = fmaxf(mx1, __shfl_xor_sync(0xffffffffu, mx1, 1));
        mx1 = fmaxf(mx1, __shfl_xor_sync(0xffffffffu, mx1, 2));
        const float mn0 = fmaxf(M0, mx0), mn1 = fmaxf(M1, mx1);
        const float sc0 = __expf(M0 - mn0), sc1 = __expf(M1 - mn1);
        float sum0 = 0.f, sum1 = 0.f;
        #pragma unroll
        for (int n = 0; n < 8; n++) {
            sreg[n][0] = __expf(sreg[n][0] - mn0); sum0 += sreg[n][0];
            sreg[n][1] = __expf(sreg[n][1] - mn0); sum0 += sreg[n][1];
            sreg[n][2] = __expf(sreg[n][2] - mn1); sum1 += sreg[n][2];
            sreg[n][3] = __expf(sreg[n][3] - mn1); sum1 += sreg[n][3];
        }
        sum0 += __shfl_xor_sync(0xffffffffu, sum0, 1);
        sum0 += __shfl_xor_sync(0xffffffffu, sum0, 2);
        sum1 += __shfl_xor_sync(0xffffffffu, sum1, 1);
        sum1 += __shfl_xor_sync(0xffffffffu, sum1, 2);
        M0 = mn0; M1 = mn1;
        L0 = L0 * sc0 + sum0;
        L1 = L1 * sc1 + sum1;
        #pragma unroll
        for (int n = 0; n < 16; n++) {
            oreg[n][0] *= sc0; oreg[n][1] *= sc0;
            oreg[n][2] *= sc1; oreg[n][3] *= sc1;
        }

        #pragma unroll
        for (int ka = 0; ka < 8; ka++) {
            const float v00 = sreg[ka][0], v01 = sreg[ka][1];
            const float v10 = sreg[ka][2], v11 = sreg[ka][3];
            float w0 = __shfl_sync(0xffffffffu, v00, srcA);
            float w1 = __shfl_sync(0xffffffffu, v01, srcA);
            float w2 = __shfl_sync(0xffffffffu, v10, srcA);
            float w3 = __shfl_sync(0xffffffffu, v11, srcA);
            float w4 = __shfl_sync(0xffffffffu, v00, srcB);
            float w5 = __shfl_sync(0xffffffffu, v01, srcB);
            float w6 = __shfl_sync(0xffffffffu, v10, srcB);
            float w7 = __shfl_sync(0xffffffffu, v11, srcB);
            const uint32_t a0 = f2tf32(odd ? w1 : w0);
            const uint32_t a1 = f2tf32(odd ? w3 : w2);
            const uint32_t a2 = f2tf32(odd ? w5 : w4);
            const uint32_t a3 = f2tf32(odd ? w7 : w6);
            const int kr0 = (ka*8 + t) * F6_VSTR;
            const int kr1 = (ka*8 + t + 4) * F6_VSTR;
            #pragma unroll
            for (int n = 0; n < 16; n++) {
                const int vc = n*8 + g;
                mma_tf32(oreg[n], a0, a1, a2, a3, uV[kr0 + vc], uV[kr1 + vc]);
            }
        }

        s_cur = (s_cur == 2) ? 0 : s_cur + 1;
        s_pre = (s_pre == 2) ? 0 : s_pre + 1;
    }

    // epilogue: emit tf32-rounded (A-operand of Wo GEMM; same rounding as before)
    const float inv0 = 1.f / L0, inv1 = 1.f / L1;
    const size_t row0 = (size_t)b * Tc + qb * 128 + r0;
    #pragma unroll
    for (int n = 0; n < 16; n++) {
        const int col = h * 128 + n*8 + 2*t;
        *(float2*)(Out +  row0      * 2048 + col) =
            make_float2(tf32r(oreg[n][0]*inv0), tf32r(oreg[n][1]*inv0));
        *(float2*)(Out + (row0 + 8) * 2048 + col) =
            make_float2(tf32r(oreg[n][2]*inv1), tf32r(oreg[n][3]*inv1));
    }
}

// ---------------- host launch --------------------------------------------------
extern "C" void kernel_launch(void* const* d_in, const int* in_sizes, int n_in,
                              void* d_out, int out_size) {
    const float* x          = (const float*)d_in[0];
    const float* Wq_sem     = (const float*)d_in[1];
    const float* Wk_sem     = (const float*)d_in[2];
    const float* Wq_geo     = (const float*)d_in[3];
    const float* Wk_geo     = (const float*)d_in[4];
    const float* Wv         = (const float*)d_in[5];
    const float* Wo         = (const float*)d_in[6];
    const float* gate_logit = (const float*)d_in[7];
    const int*   pos_offset = (const int*)d_in[8];
    float* out = (float*)d_out;

    float *qs, *ks, *qg, *kg, *vt, *qcat, *kt, *ao;
    float *xr, *wqs, *wks, *wqg, *wkg, *wv, *wo;
    cudaGetSymbolAddress((void**)&qs,   g_qs);
    cudaGetSymbolAddress((void**)&ks,   g_ks);
    cudaGetSymbolAddress((void**)&qg,   g_qg);
    cudaGetSymbolAddress((void**)&kg,   g_kg);
    cudaGetSymbolAddress((void**)&vt,   g_vt);
    cudaGetSymbolAddress((void**)&qcat, g_qcat);
    cudaGetSymbolAddress((void**)&kt,   g_kt);
    cudaGetSymbolAddress((void**)&ao,   g_ao);
    cudaGetSymbolAddress((void**)&xr,   g_xr);
    cudaGetSymbolAddress((void**)&wqs,  g_wqs);
    cudaGetSymbolAddress((void**)&wks,  g_wks);
    cudaGetSymbolAddress((void**)&wqg,  g_wqg);
    cudaGetSymbolAddress((void**)&wkg,  g_wkg);
    cudaGetSymbolAddress((void**)&wv,   g_wv);
    cudaGetSymbolAddress((void**)&wo,   g_wo);

    // 1. pre-round x + weights to tf32 (bit-identical to in-kernel cvt)
    round_all<<<dim3(256, 1, 7), 256>>>(x, Wq_sem, Wk_sem, Wq_geo, Wk_geo, Wv, Wo,
                                        xr, wqs, wks, wqg, wkg, wv, wo);

    // 2. all 5 projections in one launch
    cudaFuncSetAttribute(gemm3_proj, cudaFuncAttributeMaxDynamicSharedMemorySize,
                         G3_SMEM_BYTES);
    gemm3_proj<<<dim3(1024/128, MROWS/128, 6), 128, G3_SMEM_BYTES>>>(
        xr, wqs, wks, wqg, wkg, wv, qs, ks, qg, kg, vt);

    // 3. RoPE + gate + scale fusion; Q and K emitted tf32-rounded
    fuse_rope<<<(Bc * Hc * Tc) / 4, 256>>>(qs, ks, qg, kg, gate_logit, pos_offset,
                                           qcat, kt);

    // 4. flash attention (causal)
    cudaFuncSetAttribute(flash6, cudaFuncAttributeMaxDynamicSharedMemorySize,
                         F6_SMEM_BYTES);
    flash6<<<dim3(Tc / 128, Bc * Hc), 256, F6_SMEM_BYTES>>>(qcat, kt, vt, ao);

    // 5. output projection
    cudaFuncSetAttribute(gemm3, cudaFuncAttributeMaxDynamicSharedMemorySize,
                         G3_SMEM_BYTES);
    gemm3<<<dim3(2048/128, MROWS/128), 128, G3_SMEM_BYTES>>>(
        ao, wo, out, 2048, 2048, 2048, 0);
}

// round 11
// speedup vs baseline: 1.0287x; 1.0287x over previous
#include <cuda_runtime.h>
#include <math.h>
#include <stdint.h>

// Problem constants
#define Bc 2
#define Tc 2048
#define Dc 2048
#define Hc 16
#define MROWS (Bc*Tc)          // 4096

// ---------------- scratch (device globals; no allocation allowed) -------------
__device__ float g_qs[MROWS * 1024];
__device__ float g_ks[MROWS * 1024];
__device__ float g_qg[MROWS * 1024];
__device__ float g_kg[MROWS * 1024];
__device__ float g_vt[MROWS * 2048];           // V, tf32-rounded
__device__ float g_qcat[Bc*Hc*Tc*128];         // Q, tf32-rounded
__device__ float g_kt  [Bc*Hc*Tc*128];         // K, tf32-rounded
__device__ float g_ao [MROWS * 2048];

// ---------------- tf32 helpers -------------------------------------------------
__device__ __forceinline__ uint32_t f2tf32(float f) {
    uint32_t u;
    asm("cvt.rna.tf32.f32 %0, %1;" : "=r"(u) : "f"(f));
    return u;
}
__device__ __forceinline__ float tf32r(float x) {
    return __uint_as_float(f2tf32(x));
}

__device__ __forceinline__ void mma_tf32(float* c,
                                         uint32_t a0, uint32_t a1, uint32_t a2, uint32_t a3,
                                         uint32_t b0, uint32_t b1) {
    asm volatile("mma.sync.aligned.m16n8k8.row.col.f32.tf32.tf32.f32 "
                 "{%0,%1,%2,%3}, {%4,%5,%6,%7}, {%8,%9}, {%0,%1,%2,%3};"
                 : "+f"(c[0]), "+f"(c[1]), "+f"(c[2]), "+f"(c[3])
                 : "r"(a0), "r"(a1), "r"(a2), "r"(a3), "r"(b0), "r"(b1));
}

__device__ __forceinline__ void cp16(void* dst, const void* src) {
    uint32_t d = (uint32_t)__cvta_generic_to_shared(dst);
    asm volatile("cp.async.cg.shared.global [%0], [%1], 16;" :: "r"(d), "l"(src));
}
__device__ __forceinline__ void cp_commit() {
    asm volatile("cp.async.commit_group;");
}
__device__ __forceinline__ void cp_wait1() {
    asm volatile("cp.async.wait_group 1;");
}
__device__ __forceinline__ void cp_wait0() {
    asm volatile("cp.async.wait_group 0;");
}

// ---------------- gemm4: CTA tile 128x256, 8 warps (2x4 of 64x64) --------------
// Warp-level identical to the proven R7/R9 core. BK=16, double-buffered.
#define G4_ASTR 132
#define G4_BSTR 264
#define G4_ABUF (16*G4_ASTR)            // one buffer: 16 k-rows x 132
#define G4_BBUF (16*G4_BSTR)
#define G4_SMEM_WORDS (2*G4_ABUF + 2*G4_BBUF)
#define G4_SMEM_BYTES (G4_SMEM_WORDS*4)  // 50,688 B

__device__ __forceinline__ void gemm4_core(
    const float* __restrict__ A, const float* __restrict__ B,
    float* __restrict__ C, int K, int ldb, int ldc, int roundC,
    uint32_t* sm, int bm, int bn)
{
    uint32_t (*As)[G4_ASTR] = (uint32_t (*)[G4_ASTR])sm;                 // [32][132]
    uint32_t (*Bs)[G4_BSTR] = (uint32_t (*)[G4_BSTR])(sm + 2*G4_ABUF);   // [32][264]

    const int tid  = threadIdx.x;
    const int lane = tid & 31;
    const int wid  = tid >> 5;
    const int warpRow = (wid >> 2) * 64;   // 0 or 64
    const int warpCol = (wid & 3) * 64;    // 0,64,128,192
    const int g = lane >> 2;
    const int t = lane & 3;

    // gmem load mapping
    const int a_row = tid >> 1;            // 0..127
    const int a_c8  = (tid & 1) * 8;       // 0 or 8
    const int b_row = tid >> 4;            // 0..15
    const int b_c   = (tid & 15) * 4;      // 0..60 (4-float column base)

    float acc[4][8][4];
    #pragma unroll
    for (int i = 0; i < 4; i++)
        #pragma unroll
        for (int j = 0; j < 8; j++)
            #pragma unroll
            for (int r = 0; r < 4; r++) acc[i][j][r] = 0.f;

    float4 pa[2], pb[4];
    const int nkt = K / 16;

    // ---- prologue: tile 0 ----
    #pragma unroll
    for (int j = 0; j < 2; j++)
        pa[j] = *(const float4*)(A + (size_t)(bm + a_row) * K + a_c8 + 4*j);
    #pragma unroll
    for (int j = 0; j < 4; j++)
        pb[j] = *(const float4*)(B + (size_t)b_row * ldb + bn + b_c + 64*j);
    #pragma unroll
    for (int j = 0; j < 2; j++) {
        As[a_c8 + 4*j + 0][a_row] = f2tf32(pa[j].x);
        As[a_c8 + 4*j + 1][a_row] = f2tf32(pa[j].y);
        As[a_c8 + 4*j + 2][a_row] = f2tf32(pa[j].z);
        As[a_c8 + 4*j + 3][a_row] = f2tf32(pa[j].w);
    }
    #pragma unroll
    for (int j = 0; j < 4; j++) {
        uint4 v = make_uint4(f2tf32(pb[j].x), f2tf32(pb[j].y),
                             f2tf32(pb[j].z), f2tf32(pb[j].w));
        *(uint4*)&Bs[b_row][b_c + 64*j] = v;
    }
    __syncthreads();

    for (int kt = 0; kt < nkt; kt++) {
        const int bo = (kt & 1) * 16;

        if (kt + 1 < nkt) {
            const int k0 = (kt + 1) * 16;
            #pragma unroll
            for (int j = 0; j < 2; j++)
                pa[j] = *(const float4*)(A + (size_t)(bm + a_row) * K + k0 + a_c8 + 4*j);
            #pragma unroll
            for (int j = 0; j < 4; j++)
                pb[j] = *(const float4*)(B + (size_t)(k0 + b_row) * ldb + bn + b_c + 64*j);
        }

        #pragma unroll
        for (int ks = 0; ks < 2; ks++) {
            const int kb = bo + ks * 8;
            uint32_t af[4][4], bf[8][2];
            #pragma unroll
            for (int am = 0; am < 4; am++) {
                const int r0 = warpRow + am*16 + g;
                af[am][0] = As[kb + t    ][r0];
                af[am][1] = As[kb + t    ][r0 + 8];
                af[am][2] = As[kb + t + 4][r0];
                af[am][3] = As[kb + t + 4][r0 + 8];
            }
            #pragma unroll
            for (int an = 0; an < 8; an++) {
                const int c0 = warpCol + an*8 + g;
                bf[an][0] = Bs[kb + t    ][c0];
                bf[an][1] = Bs[kb + t + 4][c0];
            }
            #pragma unroll
            for (int am = 0; am < 4; am++)
                #pragma unroll
                for (int an = 0; an < 8; an++)
                    mma_tf32(acc[am][an], af[am][0], af[am][1], af[am][2], af[am][3],
                             bf[an][0], bf[an][1]);
        }

        if (kt + 1 < nkt) {
            const int no = ((kt + 1) & 1) * 16;
            #pragma unroll
            for (int j = 0; j < 2; j++) {
                As[no + a_c8 + 4*j + 0][a_row] = f2tf32(pa[j].x);
                As[no + a_c8 + 4*j + 1][a_row] = f2tf32(pa[j].y);
                As[no + a_c8 + 4*j + 2][a_row] = f2tf32(pa[j].z);
                As[no + a_c8 + 4*j + 3][a_row] = f2tf32(pa[j].w);
            }
            #pragma unroll
            for (int j = 0; j < 4; j++) {
                uint4 v = make_uint4(f2tf32(pb[j].x), f2tf32(pb[j].y),
                                     f2tf32(pb[j].z), f2tf32(pb[j].w));
                *(uint4*)&Bs[no + b_row][b_c + 64*j] = v;
            }
        }
        __syncthreads();
    }

    #pragma unroll
    for (int am = 0; am < 4; am++) {
        const int r0 = bm + warpRow + am*16 + g;
        #pragma unroll
        for (int an = 0; an < 8; an++) {
            const int c0 = bn + warpCol + an*8 + t*2;
            float v0 = acc[am][an][0], v1 = acc[am][an][1];
            float v2 = acc[am][an][2], v3 = acc[am][an][3];
            if (roundC) { v0 = tf32r(v0); v1 = tf32r(v1); v2 = tf32r(v2); v3 = tf32r(v3); }
            *(float2*)(C + (size_t)r0 * ldc + c0)       = make_float2(v0, v1);
            *(float2*)(C + (size_t)(r0 + 8) * ldc + c0) = make_float2(v2, v3);
        }
    }
}

__global__ __launch_bounds__(256, 1) void gemm4(
    const float* __restrict__ A, const float* __restrict__ B,
    float* __restrict__ C, int K, int ldb, int ldc, int roundC)
{
    extern __shared__ uint32_t smw[];
    gemm4_core(A, B, C, K, ldb, ldc, roundC, smw,
               blockIdx.y * 128, blockIdx.x * 256);
}

// Batched: 4 (B, C) pairs sharing the same A — the Q/K projections (N=1024).
__global__ __launch_bounds__(256, 1) void gemm4_qk(
    const float* __restrict__ A,
    const float* __restrict__ B0, const float* __restrict__ B1,
    const float* __restrict__ B2, const float* __restrict__ B3,
    float* __restrict__ C0, float* __restrict__ C1,
    float* __restrict__ C2, float* __restrict__ C3)
{
    extern __shared__ uint32_t smw[];
    const float* B = (blockIdx.z == 0) ? B0 : (blockIdx.z == 1) ? B1
                   : (blockIdx.z == 2) ? B2 : B3;
    float* C = (blockIdx.z == 0) ? C0 : (blockIdx.z == 1) ? C1
             : (blockIdx.z == 2) ? C2 : C3;
    gemm4_core(A, B, C, 2048, 1024, 1024, 0, smw,
               blockIdx.y * 128, blockIdx.x * 256);
}

// ---------------- RoPE + gate fusion: Q and K both tf32-rounded ----------------
__global__ __launch_bounds__(256) void fuse_rope(
    const float* __restrict__ qs, const float* __restrict__ ks,
    const float* __restrict__ qg, const float* __restrict__ kg,
    const float* __restrict__ gate_logit,
    const int* __restrict__ pos_offset,
    float* __restrict__ qcat, float* __restrict__ kt_o)
{
    const int row = blockIdx.x * 4 + (threadIdx.x >> 6);   // (b*H + h)*T + t
    const int d   = threadIdx.x & 63;
    const int t   = row % Tc;
    const int h   = (row / Tc) % Hc;
    const int b   = row / (Tc * Hc);

    const size_t src = ((size_t)(b * Tc + t)) * 1024 + h * 64 + d;
    const size_t dst = (size_t)row * 128;

    const float gate = 1.f / (1.f + __expf(-gate_logit[h]));
    const float scale = 0.125f;              // 1/sqrt(64)
    const float gq_sem = 2.f * gate * scale;
    const float gq_geo = (2.f - 2.f * gate) * scale;

    qcat[dst + d] = tf32r(qs[src] * gq_sem);
    kt_o[dst + d] = tf32r(ks[src]);

    if (d < 32) {
        const float inv_freq = powf(10000.f, -(float)d / 32.f);
        const float ang = ((float)t + (float)(*pos_offset)) * inv_freq;
        const float c = cosf(ang), s = sinf(ang);
        const float q1 = qg[src], q2 = qg[src + 32];
        const float k1 = kg[src], k2 = kg[src + 32];
        qcat[dst + 64 + d]      = tf32r((q1 * c - q2 * s) * gq_geo);
        qcat[dst + 64 + d + 32] = tf32r((q2 * c + q1 * s) * gq_geo);
        kt_o[dst + 64 + d]      = tf32r(k1 * c - k2 * s);
        kt_o[dst + 64 + d + 32] = tf32r(k2 * c + k1 * s);
    }
}

// ---------------- Flash attention v6 (R9, unchanged) ---------------------------
#define F6_KSTR 132
#define F6_VSTR 136
#define F6_KBUF (64*F6_KSTR)
#define F6_VBUF (64*F6_VSTR)
#define F6_STAGE (F6_KBUF + F6_VBUF)
#define F6_SMEM_FLOATS (3 * F6_STAGE)
#define F6_SMEM_BYTES  (F6_SMEM_FLOATS * 4)   // 205,824 B

__global__ __launch_bounds__(256, 1) void flash6(
    const float* __restrict__ Qc,
    const float* __restrict__ Ktg,
    const float* __restrict__ Vtg,
    float* __restrict__ Out)
{
    extern __shared__ float sm[];

    const int qb = gridDim.x - 1 - blockIdx.x;   // heavy CTAs first
    const int bh = blockIdx.y;
    const int b  = bh >> 4, h = bh & 15;
    const int tid  = threadIdx.x;
    const int lane = tid & 31;
    const int wid  = tid >> 5;
    const int g = lane >> 2;
    const int t = lane & 3;
    const int r0 = wid * 16 + g;

    const float* Qg  = Qc  + ((size_t)bh * Tc + qb * 128) * 128;
    const float* Kp  = Ktg + (size_t)bh * Tc * 128;
    const float* Vp  = Vtg + (size_t)b * Tc * 2048 + h * 128;

    for (int i = tid; i < 4096; i += 256) {
        const int r = i >> 5, c4 = (i & 31) << 2;
        *(float4*)&sm[r * F6_KSTR + c4] = *(const float4*)(Qg + r * 128 + c4);
    }
    __syncthreads();
    uint32_t qf[16][4];
    #pragma unroll
    for (int ks = 0; ks < 16; ks++) {
        qf[ks][0] = f2tf32(sm[ r0      * F6_KSTR + ks*8 + t]);
        qf[ks][1] = f2tf32(sm[(r0 + 8) * F6_KSTR + ks*8 + t]);
        qf[ks][2] = f2tf32(sm[ r0      * F6_KSTR + ks*8 + t + 4]);
        qf[ks][3] = f2tf32(sm[(r0 + 8) * F6_KSTR + ks*8 + t + 4]);
    }
    __syncthreads();

    const int ntiles = 2 * qb + 2;

    #pragma unroll
    for (int pre = 0; pre < 2; pre++) {
        float* dK = sm + pre * F6_STAGE;
        float* dV = dK + F6_KBUF;
        #pragma unroll
        for (int j = 0; j < 8; j++) {
            const int i = tid + j * 256;
            const int r = i >> 5, c4 = (i & 31) << 2;
            const size_t krow = (size_t)(pre * 64 + r);
            cp16(&dK[r*F6_KSTR + c4], Kp + krow*128  + c4);
            cp16(&dV[r*F6_VSTR + c4], Vp + krow*2048 + c4);
        }
        cp_commit();
    }

    float oreg[16][4];
    #pragma unroll
    for (int n = 0; n < 16; n++) {
        oreg[n][0] = 0.f; oreg[n][1] = 0.f; oreg[n][2] = 0.f; oreg[n][3] = 0.f;
    }
    float M0 = -1e30f, M1 = -1e30f, L0 = 0.f, L1 = 0.f;

    const int srcA = (lane & 28) | (t >> 1);
    const int srcB = srcA + 2;
    const bool odd = (t & 1);

    int s_cur = 0, s_pre = 2;
    for (int kt = 0; kt < ntiles; kt++) {
        if (kt + 1 < ntiles) cp_wait1(); else cp_wait0();
        __syncthreads();

        if (kt + 2 < ntiles) {
            float* dK = sm + s_pre * F6_STAGE;
            float* dV = dK + F6_KBUF;
            #pragma unroll
            for (int j = 0; j < 8; j++) {
                const int i = tid + j * 256;
                const int r = i >> 5, c4 = (i & 31) << 2;
                const size_t krow = (size_t)((kt + 2) * 64 + r);
                cp16(&dK[r*F6_KSTR + c4], Kp + krow*128  + c4);
                cp16(&dV[r*F6_VSTR + c4], Vp + krow*2048 + c4);
            }
            cp_commit();
        }

        const uint32_t* uK = (const uint32_t*)(sm + s_cur * F6_STAGE);
        const uint32_t* uV = uK + F6_KBUF;

        float sreg[8][4];
        #pragma unroll
        for (int n = 0; n < 8; n++) {
            sreg[n][0] = 0.f; sreg[n][1] = 0.f; sreg[n][2] = 0.f; sreg[n][3] = 0.f;
        }
        #pragma unroll
        for (int ks = 0; ks < 16; ks++) {
            const int kb = ks*8 + t;
            #pragma unroll
            for (int n = 0; n < 8; n++) {
                const int kr = n*8 + g;
                mma_tf32(sreg[n], qf[ks][0], qf[ks][1], qf[ks][2], qf[ks][3],
                         uK[kr*F6_KSTR + kb], uK[kr*F6_KSTR + kb + 4]);
            }
        }

        if (kt >= 2 * qb) {
            const int qrow0 = qb * 128 + r0;
            const int qrow1 = qrow0 + 8;
            #pragma unroll
            for (int n = 0; n < 8; n++) {
                const int c = kt * 64 + n*8 + 2*t;
                if (c     > qrow0) sreg[n][0] = -1e30f;
                if (c + 1 > qrow0) sreg[n][1] = -1e30f;
                if (c     > qrow1) sreg[n][2] = -1e30f;
                if (c + 1 > qrow1) sreg[n][3] = -1e30f;
            }
        }

        float mx0 = -1e30f, mx1 = -1e30f;
        #pragma unroll
        for (int n = 0; n < 8; n++) {
            mx0 = fmaxf(mx0, fmaxf(sreg[n][0], sreg[n][1]));
            mx1 = fmaxf(mx1, fmaxf(sreg[n][2], sreg[n][3]));
        }
        mx0 = fmaxf(mx0, __shfl_xor_sync(0xffffffffu, mx0, 1));
        mx0 = fmaxf(mx0, __shfl_xor_sync(0xffffffffu, mx0, 2));
        mx1 = fmaxf(mx1, __shfl_xor_sync(0xffffffffu, mx1, 1));
        mx1 = fmaxf(mx1, __shfl_xor_sync(0xffffffffu, mx1, 2));
        const float mn0 = fmaxf(M0, mx0), mn1 = fmaxf(M1, mx1);
        const float sc0 = __expf(M0 - mn0), sc1 = __expf(M1 - mn1);
        float sum0 = 0.f, sum1 = 0.f;
        #pragma unroll
        for (int n = 0; n < 8; n++) {
            sreg[n][0] = __expf(sreg[n][0] - mn0); sum0 += sreg[n][0];
            sreg[n][1] = __expf(sreg[n][1] - mn0); sum0 += sreg[n][1];
            sreg[n][2] = __expf(sreg[n][2] - mn1); sum1 += sreg[n][2];
            sreg[n][3] = __expf(sreg[n][3] - mn1); sum1 += sreg[n][3];
        }
        sum0 += __shfl_xor_sync(0xffffffffu, sum0, 1);
        sum0 += __shfl_xor_sync(0xffffffffu, sum0, 2);
        sum1 += __shfl_xor_sync(0xffffffffu, sum1, 1);
        sum1 += __shfl_xor_sync(0xffffffffu, sum1, 2);
        M0 = mn0; M1 = mn1;
        L0 = L0 * sc0 + sum0;
        L1 = L1 * sc1 + sum1;
        #pragma unroll
        for (int n = 0; n < 16; n++) {
            oreg[n][0] *= sc0; oreg[n][1] *= sc0;
            oreg[n][2] *= sc1; oreg[n][3] *= sc1;
        }

        #pragma unroll
        for (int ka = 0; ka < 8; ka++) {
            const float v00 = sreg[ka][0], v01 = sreg[ka][1];
            const float v10 = sreg[ka][2], v11 = sreg[ka][3];
            float w0 = __shfl_sync(0xffffffffu, v00, srcA);
            float w1 = __shfl_sync(0xffffffffu, v01, srcA);
            float w2 = __shfl_sync(0xffffffffu, v10, srcA);
            float w3 = __shfl_sync(0xffffffffu, v11, srcA);
            float w4 = __shfl_sync(0xffffffffu, v00, srcB);
            float w5 = __shfl_sync(0xffffffffu, v01, srcB);
            float w6 = __shfl_sync(0xffffffffu, v10, srcB);
            float w7 = __shfl_sync(0xffffffffu, v11, srcB);
            const uint32_t a0 = f2tf32(odd ? w1 : w0);
            const uint32_t a1 = f2tf32(odd ? w3 : w2);
            const uint32_t a2 = f2tf32(odd ? w5 : w4);
            const uint32_t a3 = f2tf32(odd ? w7 : w6);
            const int kr0 = (ka*8 + t) * F6_VSTR;
            const int kr1 = (ka*8 + t + 4) * F6_VSTR;
            #pragma unroll
            for (int n = 0; n < 16; n++) {
                const int vc = n*8 + g;
                mma_tf32(oreg[n], a0, a1, a2, a3, uV[kr0 + vc], uV[kr1 + vc]);
            }
        }

        s_cur = (s_cur == 2) ? 0 : s_cur + 1;
        s_pre = (s_pre == 2) ? 0 : s_pre + 1;
    }

    const float inv0 = 1.f / L0, inv1 = 1.f / L1;
    const size_t row0 = (size_t)b * Tc + qb * 128 + r0;
    #pragma unroll
    for (int n = 0; n < 16; n++) {
        const int col = h * 128 + n*8 + 2*t;
        *(float2*)(Out +  row0      * 2048 + col) = make_float2(oreg[n][0]*inv0, oreg[n][1]*inv0);
        *(float2*)(Out + (row0 + 8) * 2048 + col) = make_float2(oreg[n][2]*inv1, oreg[n][3]*inv1);
    }
}

// ---------------- host launch --------------------------------------------------
extern "C" void kernel_launch(void* const* d_in, const int* in_sizes, int n_in,
                              void* d_out, int out_size) {
    const float* x          = (const float*)d_in[0];
    const float* Wq_sem     = (const float*)d_in[1];
    const float* Wk_sem     = (const float*)d_in[2];
    const float* Wq_geo     = (const float*)d_in[3];
    const float* Wk_geo     = (const float*)d_in[4];
    const float* Wv         = (const float*)d_in[5];
    const float* Wo         = (const float*)d_in[6];
    const float* gate_logit = (const float*)d_in[7];
    const int*   pos_offset = (const int*)d_in[8];
    float* out = (float*)d_out;

    float *qs, *ks, *qg, *kg, *vt, *qcat, *kt, *ao;
    cudaGetSymbolAddress((void**)&qs,   g_qs);
    cudaGetSymbolAddress((void**)&ks,   g_ks);
    cudaGetSymbolAddress((void**)&qg,   g_qg);
    cudaGetSymbolAddress((void**)&kg,   g_kg);
    cudaGetSymbolAddress((void**)&vt,   g_vt);
    cudaGetSymbolAddress((void**)&qcat, g_qcat);
    cudaGetSymbolAddress((void**)&kt,   g_kt);
    cudaGetSymbolAddress((void**)&ao,   g_ao);

    cudaFuncSetAttribute(gemm4, cudaFuncAttributeMaxDynamicSharedMemorySize,
                         G4_SMEM_BYTES);
    cudaFuncSetAttribute(gemm4_qk, cudaFuncAttributeMaxDynamicSharedMemorySize,
                         G4_SMEM_BYTES);

    // Q/K projections: one batched launch (N=1024, 128x256 tiles)
    gemm4_qk<<<dim3(1024/256, MROWS/128, 4), 256, G4_SMEM_BYTES>>>(
        x, Wq_sem, Wk_sem, Wq_geo, Wk_geo, qs, ks, qg, kg);

    // V projection (tf32-rounded epilogue)
    gemm4<<<dim3(2048/256, MROWS/128), 256, G4_SMEM_BYTES>>>(
        x, Wv, vt, 2048, 2048, 2048, 1);

    // RoPE + gate + scale fusion; Q and K emitted tf32-rounded
    fuse_rope<<<(Bc * Hc * Tc) / 4, 256>>>(qs, ks, qg, kg, gate_logit, pos_offset,
                                           qcat, kt);

    // flash attention (causal)
    cudaFuncSetAttribute(flash6, cudaFuncAttributeMaxDynamicSharedMemorySize,
                         F6_SMEM_BYTES);
    flash6<<<dim3(Tc / 128, Bc * Hc), 256, F6_SMEM_BYTES>>>(qcat, kt, vt, ao);

    // output projection
    gemm4<<<dim3(2048/256, MROWS/128), 256, G4_SMEM_BYTES>>>(
        ao, Wo, out, 2048, 2048, 2048, 0);
}

// round 15
// speedup vs baseline: 1.1707x; 1.1381x over previous
#include <cuda_runtime.h>
#include <math.h>
#include <stdint.h>

// Problem constants
#define Bc 2
#define Tc 2048
#define Dc 2048
#define Hc 16
#define MROWS (Bc*Tc)          // 4096

// ---------------- scratch (device globals; no allocation allowed) -------------
__device__ float g_qs[MROWS * 1024];
__device__ float g_ks[MROWS * 1024];
__device__ float g_qg[MROWS * 1024];
__device__ float g_kg[MROWS * 1024];
__device__ float g_vt[MROWS * 2048];           // V, tf32-rounded
__device__ float g_qcat[Bc*Hc*Tc*128];         // Q, tf32-rounded
__device__ float g_kt  [Bc*Hc*Tc*128];         // K, tf32-rounded
__device__ float g_ao [MROWS * 2048];          // attn out, tf32-rounded
// pre-rounded GEMM operands
__device__ float g_xr  [MROWS * 2048];
__device__ float g_wqs [2048 * 1024];
__device__ float g_wks [2048 * 1024];
__device__ float g_wqg [2048 * 1024];
__device__ float g_wkg [2048 * 1024];
__device__ float g_wv  [2048 * 2048];
__device__ float g_wo  [2048 * 2048];

// ---------------- tf32 helpers -------------------------------------------------
__device__ __forceinline__ uint32_t f2tf32(float f) {
    uint32_t u;
    asm("cvt.rna.tf32.f32 %0, %1;" : "=r"(u) : "f"(f));
    return u;
}
__device__ __forceinline__ float tf32r(float x) {
    return __uint_as_float(f2tf32(x));
}

__device__ __forceinline__ void mma_tf32(float* c,
                                         uint32_t a0, uint32_t a1, uint32_t a2, uint32_t a3,
                                         uint32_t b0, uint32_t b1) {
    asm volatile("mma.sync.aligned.m16n8k8.row.col.f32.tf32.tf32.f32 "
                 "{%0,%1,%2,%3}, {%4,%5,%6,%7}, {%8,%9}, {%0,%1,%2,%3};"
                 : "+f"(c[0]), "+f"(c[1]), "+f"(c[2]), "+f"(c[3])
                 : "r"(a0), "r"(a1), "r"(a2), "r"(a3), "r"(b0), "r"(b1));
}

__device__ __forceinline__ void cp16(void* dst, const void* src) {
    uint32_t d = (uint32_t)__cvta_generic_to_shared(dst);
    asm volatile("cp.async.cg.shared.global [%0], [%1], 16;" :: "r"(d), "l"(src));
}
__device__ __forceinline__ void cp_commit() {
    asm volatile("cp.async.commit_group;");
}
__device__ __forceinline__ void cp_wait1() {
    asm volatile("cp.async.wait_group 1;");
}
__device__ __forceinline__ void cp_wait0() {
    asm volatile("cp.async.wait_group 0;");
}

// ---------------- pre-round pass: tf32(RNA) copies of x and weights -----------
__global__ __launch_bounds__(256) void round_all(
    const float* __restrict__ x,
    const float* __restrict__ w0, const float* __restrict__ w1,
    const float* __restrict__ w2, const float* __restrict__ w3,
    const float* __restrict__ wv, const float* __restrict__ wo,
    float* __restrict__ xr,
    float* __restrict__ w0r, float* __restrict__ w1r,
    float* __restrict__ w2r, float* __restrict__ w3r,
    float* __restrict__ wvr, float* __restrict__ wor)
{
    const int z = blockIdx.z;
    const float* src; float* dst; int n4;
    switch (z) {
        case 0: src = x;  dst = xr;  n4 = MROWS * 2048 / 4; break;
        case 1: src = w0; dst = w0r; n4 = 2048 * 1024 / 4;  break;
        case 2: src = w1; dst = w1r; n4 = 2048 * 1024 / 4;  break;
        case 3: src = w2; dst = w2r; n4 = 2048 * 1024 / 4;  break;
        case 4: src = w3; dst = w3r; n4 = 2048 * 1024 / 4;  break;
        case 5: src = wv; dst = wvr; n4 = 2048 * 2048 / 4;  break;
        default:src = wo; dst = wor; n4 = 2048 * 2048 / 4;  break;
    }
    const int stride = gridDim.x * blockDim.x;
    for (int i = blockIdx.x * blockDim.x + threadIdx.x; i < n4; i += stride) {
        float4 v = *(const float4*)(src + (size_t)i * 4);
        v.x = tf32r(v.x); v.y = tf32r(v.y); v.z = tf32r(v.z); v.w = tf32r(v.w);
        *(float4*)(dst + (size_t)i * 4) = v;
    }
}

// ---------------- gemm5: R9 core, pre-rounded operands, vectorized STS ---------
// 128 threads, warp tile 64x64, CTA 128x128, BK=16, double-buffered, 1 sync/iter.
// A staged ROW-major [128][20] (conflict-free frag reads), B [16][136].
#define TBK 16
#define G5_ASTR 20

__device__ __forceinline__ void gemm5_core(
    const float* __restrict__ A, const float* __restrict__ B,
    float* __restrict__ C, int K, int ldb, int ldc, int roundC,
    int bm, int bn)
{
    __shared__ float As[2][128][G5_ASTR];    // 20,480 B
    __shared__ float Bs[2][TBK][136];        // 17,408 B

    const int tid  = threadIdx.x;
    const int lane = tid & 31;
    const int wid  = tid >> 5;
    const int warpRow = (wid >> 1) * 64;
    const int warpCol = (wid & 1) * 64;
    const int g = lane >> 2;
    const int t = lane & 3;

    // gmem load mapping (R9 mappings, float4 stores)
    const int a_r0 = tid >> 2;            // 0..31; rows a_r0 + 32*i
    const int a_c4 = (tid & 3) * 4;       // 0,4,8,12
    const int b_n4 = (tid & 31) * 4;
    const int b_k0 = tid >> 5;            // rows b_k0 + 4*i

    float acc[4][8][4];
    #pragma unroll
    for (int i = 0; i < 4; i++)
        #pragma unroll
        for (int j = 0; j < 8; j++)
            #pragma unroll
            for (int r = 0; r < 4; r++) acc[i][j][r] = 0.f;

    float4 pa[4], pb[4];
    const int nkt = K / TBK;

    // ---- prologue: tile 0 ----
    #pragma unroll
    for (int i = 0; i < 4; i++)
        pa[i] = *(const float4*)(A + (size_t)(bm + a_r0 + 32*i) * K + a_c4);
    #pragma unroll
    for (int i = 0; i < 4; i++)
        pb[i] = *(const float4*)(B + (size_t)(b_k0 + 4*i) * ldb + bn + b_n4);
    #pragma unroll
    for (int i = 0; i < 4; i++)
        *(float4*)&As[0][a_r0 + 32*i][a_c4] = pa[i];
    #pragma unroll
    for (int i = 0; i < 4; i++)
        *(float4*)&Bs[0][b_k0 + 4*i][b_n4] = pb[i];
    __syncthreads();

    for (int kt = 0; kt < nkt; kt++) {
        const int buf = kt & 1;

        if (kt + 1 < nkt) {
            const int k0 = (kt + 1) * TBK;
            #pragma unroll
            for (int i = 0; i < 4; i++)
                pa[i] = *(const float4*)(A + (size_t)(bm + a_r0 + 32*i) * K + k0 + a_c4);
            #pragma unroll
            for (int i = 0; i < 4; i++)
                pb[i] = *(const float4*)(B + (size_t)(k0 + b_k0 + 4*i) * ldb + bn + b_n4);
        }

        const uint32_t* uA = (const uint32_t*)&As[buf][0][0];
        const uint32_t* uB = (const uint32_t*)&Bs[buf][0][0];

        #pragma unroll
        for (int ks = 0; ks < 2; ks++) {
            const int kb = ks * 8;
            uint32_t af[4][4], bf[8][2];
            #pragma unroll
            for (int am = 0; am < 4; am++) {
                const int r0 = warpRow + am*16 + g;
                af[am][0] = uA[ r0      * G5_ASTR + kb + t];
                af[am][1] = uA[(r0 + 8) * G5_ASTR + kb + t];
                af[am][2] = uA[ r0      * G5_ASTR + kb + t + 4];
                af[am][3] = uA[(r0 + 8) * G5_ASTR + kb + t + 4];
            }
            #pragma unroll
            for (int an = 0; an < 8; an++) {
                const int c0 = warpCol + an*8 + g;
                bf[an][0] = uB[(kb + t    ) * 136 + c0];
                bf[an][1] = uB[(kb + t + 4) * 136 + c0];
            }
            #pragma unroll
            for (int am = 0; am < 4; am++)
                #pragma unroll
                for (int an = 0; an < 8; an++)
                    mma_tf32(acc[am][an], af[am][0], af[am][1], af[am][2], af[am][3],
                             bf[an][0], bf[an][1]);
        }

        if (kt + 1 < nkt) {
            const int nb = buf ^ 1;
            #pragma unroll
            for (int i = 0; i < 4; i++)
                *(float4*)&As[nb][a_r0 + 32*i][a_c4] = pa[i];
            #pragma unroll
            for (int i = 0; i < 4; i++)
                *(float4*)&Bs[nb][b_k0 + 4*i][b_n4] = pb[i];
        }
        __syncthreads();
    }

    #pragma unroll
    for (int am = 0; am < 4; am++) {
        const int r0 = bm + warpRow + am*16 + g;
        #pragma unroll
        for (int an = 0; an < 8; an++) {
            const int c0 = bn + warpCol + an*8 + t*2;
            float v0 = acc[am][an][0], v1 = acc[am][an][1];
            float v2 = acc[am][an][2], v3 = acc[am][an][3];
            if (roundC) { v0 = tf32r(v0); v1 = tf32r(v1); v2 = tf32r(v2); v3 = tf32r(v3); }
            *(float2*)(C + (size_t)r0 * ldc + c0)       = make_float2(v0, v1);
            *(float2*)(C + (size_t)(r0 + 8) * ldc + c0) = make_float2(v2, v3);
        }
    }
}

__global__ __launch_bounds__(128, 2) void gemm5(
    const float* __restrict__ A, const float* __restrict__ B,
    float* __restrict__ C, int K, int ldb, int ldc, int roundC)
{
    gemm5_core(A, B, C, K, ldb, ldc, roundC, blockIdx.y * 128, blockIdx.x * 128);
}

// Batched: 4 (B, C) pairs sharing the same A — the Q/K projections (N=1024).
__global__ __launch_bounds__(128, 2) void gemm5_qk(
    const float* __restrict__ A,
    const float* __restrict__ B0, const float* __restrict__ B1,
    const float* __restrict__ B2, const float* __restrict__ B3,
    float* __restrict__ C0, float* __restrict__ C1,
    float* __restrict__ C2, float* __restrict__ C3)
{
    const float* B = (blockIdx.z == 0) ? B0 : (blockIdx.z == 1) ? B1
                   : (blockIdx.z == 2) ? B2 : B3;
    float* C = (blockIdx.z == 0) ? C0 : (blockIdx.z == 1) ? C1
             : (blockIdx.z == 2) ? C2 : C3;
    gemm5_core(A, B, C, 2048, 1024, 1024, 0, blockIdx.y * 128, blockIdx.x * 128);
}

// ---------------- RoPE + gate fusion: Q and K both tf32-rounded ----------------
__global__ __launch_bounds__(256) void fuse_rope(
    const float* __restrict__ qs, const float* __restrict__ ks,
    const float* __restrict__ qg, const float* __restrict__ kg,
    const float* __restrict__ gate_logit,
    const int* __restrict__ pos_offset,
    float* __restrict__ qcat, float* __restrict__ kt_o)
{
    const int row = blockIdx.x * 4 + (threadIdx.x >> 6);   // (b*H + h)*T + t
    const int d   = threadIdx.x & 63;
    const int t   = row % Tc;
    const int h   = (row / Tc) % Hc;
    const int b   = row / (Tc * Hc);

    const size_t src = ((size_t)(b * Tc + t)) * 1024 + h * 64 + d;
    const size_t dst = (size_t)row * 128;

    const float gate = 1.f / (1.f + __expf(-gate_logit[h]));
    const float scale = 0.125f;              // 1/sqrt(64)
    const float gq_sem = 2.f * gate * scale;
    const float gq_geo = (2.f - 2.f * gate) * scale;

    qcat[dst + d] = tf32r(qs[src] * gq_sem);
    kt_o[dst + d] = tf32r(ks[src]);

    if (d < 32) {
        const float inv_freq = powf(10000.f, -(float)d / 32.f);
        const float ang = ((float)t + (float)(*pos_offset)) * inv_freq;
        const float c = cosf(ang), s = sinf(ang);
        const float q1 = qg[src], q2 = qg[src + 32];
        const float k1 = kg[src], k2 = kg[src + 32];
        qcat[dst + 64 + d]      = tf32r((q1 * c - q2 * s) * gq_geo);
        qcat[dst + 64 + d + 32] = tf32r((q2 * c + q1 * s) * gq_geo);
        kt_o[dst + 64 + d]      = tf32r(k1 * c - k2 * s);
        kt_o[dst + 64 + d + 32] = tf32r(k2 * c + k1 * s);
    }
}

// ---------------- Flash attention v6 (R9 core; epilogue emits tf32-rounded) ----
#define F6_KSTR 132
#define F6_VSTR 136
#define F6_KBUF (64*F6_KSTR)
#define F6_VBUF (64*F6_VSTR)
#define F6_STAGE (F6_KBUF + F6_VBUF)
#define F6_SMEM_FLOATS (3 * F6_STAGE)
#define F6_SMEM_BYTES  (F6_SMEM_FLOATS * 4)   // 205,824 B

__global__ __launch_bounds__(256, 1) void flash6(
    const float* __restrict__ Qc,
    const float* __restrict__ Ktg,
    const float* __restrict__ Vtg,
    float* __restrict__ Out)
{
    extern __shared__ float sm[];

    const int qb = gridDim.x - 1 - blockIdx.x;   // heavy CTAs first
    const int bh = blockIdx.y;
    const int b  = bh >> 4, h = bh & 15;
    const int tid  = threadIdx.x;
    const int lane = tid & 31;
    const int wid  = tid >> 5;
    const int g = lane >> 2;
    const int t = lane & 3;
    const int r0 = wid * 16 + g;

    const float* Qg  = Qc  + ((size_t)bh * Tc + qb * 128) * 128;
    const float* Kp  = Ktg + (size_t)bh * Tc * 128;
    const float* Vp  = Vtg + (size_t)b * Tc * 2048 + h * 128;

    for (int i = tid; i < 4096; i += 256) {
        const int r = i >> 5, c4 = (i & 31) << 2;
        *(float4*)&sm[r * F6_KSTR + c4] = *(const float4*)(Qg + r * 128 + c4);
    }
    __syncthreads();
    uint32_t qf[16][4];
    #pragma unroll
    for (int ks = 0; ks < 16; ks++) {
        qf[ks][0] = f2tf32(sm[ r0      * F6_KSTR + ks*8 + t]);
        qf[ks][1] = f2tf32(sm[(r0 + 8) * F6_KSTR + ks*8 + t]);
        qf[ks][2] = f2tf32(sm[ r0      * F6_KSTR + ks*8 + t + 4]);
        qf[ks][3] = f2tf32(sm[(r0 + 8) * F6_KSTR + ks*8 + t + 4]);
    }
    __syncthreads();

    const int ntiles = 2 * qb + 2;

    #pragma unroll
    for (int pre = 0; pre < 2; pre++) {
        float* dK = sm + pre * F6_STAGE;
        float* dV = dK + F6_KBUF;
        #pragma unroll
        for (int j = 0; j < 8; j++) {
            const int i = tid + j * 256;
            const int r = i >> 5, c4 = (i & 31) << 2;
            const size_t krow = (size_t)(pre * 64 + r);
            cp16(&dK[r*F6_KSTR + c4], Kp + krow*128  + c4);
            cp16(&dV[r*F6_VSTR + c4], Vp + krow*2048 + c4);
        }
        cp_commit();
    }

    float oreg[16][4];
    #pragma unroll
    for (int n = 0; n < 16; n++) {
        oreg[n][0] = 0.f; oreg[n][1] = 0.f; oreg[n][2] = 0.f; oreg[n][3] = 0.f;
    }
    float M0 = -1e30f, M1 = -1e30f, L0 = 0.f, L1 = 0.f;

    const int srcA = (lane & 28) | (t >> 1);
    const int srcB = srcA + 2;
    const bool odd = (t & 1);

    int s_cur = 0, s_pre = 2;
    for (int kt = 0; kt < ntiles; kt++) {
        if (kt + 1 < ntiles) cp_wait1(); else cp_wait0();
        __syncthreads();

        if (kt + 2 < ntiles) {
            float* dK = sm + s_pre * F6_STAGE;
            float* dV = dK + F6_KBUF;
            #pragma unroll
            for (int j = 0; j < 8; j++) {
                const int i = tid + j * 256;
                const int r = i >> 5, c4 = (i & 31) << 2;
                const size_t krow = (size_t)((kt + 2) * 64 + r);
                cp16(&dK[r*F6_KSTR + c4], Kp + krow*128  + c4);
                cp16(&dV[r*F6_VSTR + c4], Vp + krow*2048 + c4);
            }
            cp_commit();
        }

        const uint32_t* uK = (const uint32_t*)(sm + s_cur * F6_STAGE);
        const uint32_t* uV = uK + F6_KBUF;

        float sreg[8][4];
        #pragma unroll
        for (int n = 0; n < 8; n++) {
            sreg[n][0] = 0.f; sreg[n][1] = 0.f; sreg[n][2] = 0.f; sreg[n][3] = 0.f;
        }
        #pragma unroll
        for (int ks = 0; ks < 16; ks++) {
            const int kb = ks*8 + t;
            #pragma unroll
            for (int n = 0; n < 8; n++) {
                const int kr = n*8 + g;
                mma_tf32(sreg[n], qf[ks][0], qf[ks][1], qf[ks][2], qf[ks][3],
                         uK[kr*F6_KSTR + kb], uK[kr*F6_KSTR + kb + 4]);
            }
        }

        if (kt >= 2 * qb) {
            const int qrow0 = qb * 128 + r0;
            const int qrow1 = qrow0 + 8;
            #pragma unroll
            for (int n = 0; n < 8; n++) {
                const int c = kt * 64 + n*8 + 2*t;
                if (c     > qrow0) sreg[n][0] = -1e30f;
                if (c + 1 > qrow0) sreg[n][1] = -1e30f;
                if (c     > qrow1) sreg[n][2] = -1e30f;
                if (c + 1 > qrow1) sreg[n][3] = -1e30f;
            }
        }

        float mx0 = -1e30f, mx1 = -1e30f;
        #pragma unroll
        for (int n = 0; n < 8; n++) {
            mx0 = fmaxf(mx0, fmaxf(sreg[n][0], sreg[n][1]));
            mx1 = fmaxf(mx1, fmaxf(sreg[n][2], sreg[n][3]));
        }
        mx0 = fmaxf(mx0, __shfl_xor_sync(0xffffffffu, mx0, 1));
        mx0 = fmaxf(mx0, __shfl_xor_sync(0xffffffffu, mx0, 2));
        mx1 = fmaxf(mx1, __shfl_xor_sync(0xffffffffu, mx1, 1));
        mx1 = fmaxf(mx1, __shfl_xor_sync(0xffffffffu, mx1, 2));
        const float mn0 = fmaxf(M0, mx0), mn1 = fmaxf(M1, mx1);
        const float sc0 = __expf(M0 - mn0), sc1 = __expf(M1 - mn1);
        float sum0 = 0.f, sum1 = 0.f;
        #pragma unroll
        for (int n = 0; n < 8; n++) {
            sreg[n][0] = __expf(sreg[n][0] - mn0); sum0 += sreg[n][0];
            sreg[n][1] = __expf(sreg[n][1] - mn0); sum0 += sreg[n][1];
            sreg[n][2] = __expf(sreg[n][2] - mn1); sum1 += sreg[n][2];
            sreg[n][3] = __expf(sreg[n][3] - mn1); sum1 += sreg[n][3];
        }
        sum0 += __shfl_xor_sync(0xffffffffu, sum0, 1);
        sum0 += __shfl_xor_sync(0xffffffffu, sum0, 2);
        sum1 += __shfl_xor_sync(0xffffffffu, sum1, 1);
        sum1 += __shfl_xor_sync(0xffffffffu, sum1, 2);
        M0 = mn0; M1 = mn1;
        L0 = L0 * sc0 + sum0;
        L1 = L1 * sc1 + sum1;
        #pragma unroll
        for (int n = 0; n < 16; n++) {
            oreg[n][0] *= sc0; oreg[n][1] *= sc0;
            oreg[n][2] *= sc1; oreg[n][3] *= sc1;
        }

        #pragma unroll
        for (int ka = 0; ka < 8; ka++) {
            const float v00 = sreg[ka][0], v01 = sreg[ka][1];
            const float v10 = sreg[ka][2], v11 = sreg[ka][3];
            float w0 = __shfl_sync(0xffffffffu, v00, srcA);
            float w1 = __shfl_sync(0xffffffffu, v01, srcA);
            float w2 = __shfl_sync(0xffffffffu, v10, srcA);
            float w3 = __shfl_sync(0xffffffffu, v11, srcA);
            float w4 = __shfl_sync(0xffffffffu, v00, srcB);
            float w5 = __shfl_sync(0xffffffffu, v01, srcB);
            float w6 = __shfl_sync(0xffffffffu, v10, srcB);
            float w7 = __shfl_sync(0xffffffffu, v11, srcB);
            const uint32_t a0 = f2tf32(odd ? w1 : w0);
            const uint32_t a1 = f2tf32(odd ? w3 : w2);
            const uint32_t a2 = f2tf32(odd ? w5 : w4);
            const uint32_t a3 = f2tf32(odd ? w7 : w6);
            const int kr0 = (ka*8 + t) * F6_VSTR;
            const int kr1 = (ka*8 + t + 4) * F6_VSTR;
            #pragma unroll
            for (int n = 0; n < 16; n++) {
                const int vc = n*8 + g;
                mma_tf32(oreg[n], a0, a1, a2, a3, uV[kr0 + vc], uV[kr1 + vc]);
            }
        }

        s_cur = (s_cur == 2) ? 0 : s_cur + 1;
        s_pre = (s_pre == 2) ? 0 : s_pre + 1;
    }

    // epilogue: emit tf32-rounded (replaces the Wo-gemm's in-kernel cvt; same op)
    const float inv0 = 1.f / L0, inv1 = 1.f / L1;
    const size_t row0 = (size_t)b * Tc + qb * 128 + r0;
    #pragma unroll
    for (int n = 0; n < 16; n++) {
        const int col = h * 128 + n*8 + 2*t;
        *(float2*)(Out +  row0      * 2048 + col) =
            make_float2(tf32r(oreg[n][0]*inv0), tf32r(oreg[n][1]*inv0));
        *(float2*)(Out + (row0 + 8) * 2048 + col) =
            make_float2(tf32r(oreg[n][2]*inv1), tf32r(oreg[n][3]*inv1));
    }
}

// ---------------- host launch --------------------------------------------------
extern "C" void kernel_launch(void* const* d_in, const int* in_sizes, int n_in,
                              void* d_out, int out_size) {
    const float* x          = (const float*)d_in[0];
    const float* Wq_sem     = (const float*)d_in[1];
    const float* Wk_sem     = (const float*)d_in[2];
    const float* Wq_geo     = (const float*)d_in[3];
    const float* Wk_geo     = (const float*)d_in[4];
    const float* Wv         = (const float*)d_in[5];
    const float* Wo         = (const float*)d_in[6];
    const float* gate_logit = (const float*)d_in[7];
    const int*   pos_offset = (const int*)d_in[8];
    float* out = (float*)d_out;

    float *qs, *ks, *qg, *kg, *vt, *qcat, *kt, *ao;
    float *xr, *wqs, *wks, *wqg, *wkg, *wv, *wo;
    cudaGetSymbolAddress((void**)&qs,   g_qs);
    cudaGetSymbolAddress((void**)&ks,   g_ks);
    cudaGetSymbolAddress((void**)&qg,   g_qg);
    cudaGetSymbolAddress((void**)&kg,   g_kg);
    cudaGetSymbolAddress((void**)&vt,   g_vt);
    cudaGetSymbolAddress((void**)&qcat, g_qcat);
    cudaGetSymbolAddress((void**)&kt,   g_kt);
    cudaGetSymbolAddress((void**)&ao,   g_ao);
    cudaGetSymbolAddress((void**)&xr,   g_xr);
    cudaGetSymbolAddress((void**)&wqs,  g_wqs);
    cudaGetSymbolAddress((void**)&wks,  g_wks);
    cudaGetSymbolAddress((void**)&wqg,  g_wqg);
    cudaGetSymbolAddress((void**)&wkg,  g_wkg);
    cudaGetSymbolAddress((void**)&wv,   g_wv);
    cudaGetSymbolAddress((void**)&wo,   g_wo);

    // 1. pre-round x + weights to tf32 (bit-identical to the old in-kernel cvt)
    round_all<<<dim3(256, 1, 7), 256>>>(x, Wq_sem, Wk_sem, Wq_geo, Wk_geo, Wv, Wo,
                                        xr, wqs, wks, wqg, wkg, wv, wo);

    // 2. Q/K projections: one batched launch (N=1024 x4), proven 4-warp core
    gemm5_qk<<<dim3(1024/128, MROWS/128, 4), 128>>>(
        xr, wqs, wks, wqg, wkg, qs, ks, qg, kg);

    // 3. V projection (tf32-rounded epilogue)
    gemm5<<<dim3(2048/128, MROWS/128), 128>>>(xr, wv, vt, 2048, 2048, 2048, 1);

    // 4. RoPE + gate + scale fusion; Q and K emitted tf32-rounded
    fuse_rope<<<(Bc * Hc * Tc) / 4, 256>>>(qs, ks, qg, kg, gate_logit, pos_offset,
                                           qcat, kt);

    // 5. flash attention (causal)
    cudaFuncSetAttribute(flash6, cudaFuncAttributeMaxDynamicSharedMemorySize,
                         F6_SMEM_BYTES);
    flash6<<<dim3(Tc / 128, Bc * Hc), 256, F6_SMEM_BYTES>>>(qcat, kt, vt, ao);

    // 6. output projection
    gemm5<<<dim3(2048/128, MROWS/128), 128>>>(ao, wo, out, 2048, 2048, 2048, 0);
}